// round 2
// baseline (speedup 1.0000x reference)
#include <cuda_runtime.h>
#include <cstdint>
#include <cstddef>

#define BROWS   8192
#define DIN     2048
#define DSTATE  2048
#define NSEG    4

#define BM 128
#define BN 32          // state-cols per block (x4 segments concurrently)
#define BK 16
#define NK (DIN / BK)  // 128
#define SROW 20        // smem row stride in floats (16 data + 4 pad, conflict-free)

__device__ float g_gates[BROWS * NSEG];

// ---------------------------------------------------------------------------
// Gate kernel: gates[b,s] = sigmoid(x[b,:] . W_gate[s,:] + b_gate[s])
// ---------------------------------------------------------------------------
__global__ __launch_bounds__(256) void gate_kernel(const float* __restrict__ x,
                                                   const float* __restrict__ Wg,
                                                   const float* __restrict__ bg) {
    int warp = threadIdx.x >> 5;
    int lane = threadIdx.x & 31;
    int b = blockIdx.x * 8 + warp;
    const float* xr = x + (size_t)b * DIN;

    float a0 = 0.f, a1 = 0.f, a2 = 0.f, a3 = 0.f;
    for (int i = lane * 4; i < DIN; i += 32 * 4) {
        float4 xv = *(const float4*)(xr + i);
        float4 w0 = *(const float4*)(Wg + 0 * DIN + i);
        float4 w1 = *(const float4*)(Wg + 1 * DIN + i);
        float4 w2 = *(const float4*)(Wg + 2 * DIN + i);
        float4 w3 = *(const float4*)(Wg + 3 * DIN + i);
        a0 += xv.x * w0.x + xv.y * w0.y + xv.z * w0.z + xv.w * w0.w;
        a1 += xv.x * w1.x + xv.y * w1.y + xv.z * w1.z + xv.w * w1.w;
        a2 += xv.x * w2.x + xv.y * w2.y + xv.z * w2.z + xv.w * w2.w;
        a3 += xv.x * w3.x + xv.y * w3.y + xv.z * w3.z + xv.w * w3.w;
    }
#pragma unroll
    for (int off = 16; off; off >>= 1) {
        a0 += __shfl_xor_sync(0xFFFFFFFFu, a0, off);
        a1 += __shfl_xor_sync(0xFFFFFFFFu, a1, off);
        a2 += __shfl_xor_sync(0xFFFFFFFFu, a2, off);
        a3 += __shfl_xor_sync(0xFFFFFFFFu, a3, off);
    }
    if (lane == 0) {
        g_gates[b * 4 + 0] = 1.f / (1.f + __expf(-(a0 + bg[0])));
        g_gates[b * 4 + 1] = 1.f / (1.f + __expf(-(a1 + bg[1])));
        g_gates[b * 4 + 2] = 1.f / (1.f + __expf(-(a2 + bg[2])));
        g_gates[b * 4 + 3] = 1.f / (1.f + __expf(-(a3 + bg[3])));
    }
}

// ---------------------------------------------------------------------------
// Helpers
// ---------------------------------------------------------------------------
__device__ __forceinline__ uint32_t f2tf(float f) {
    uint32_t u;
    asm("cvt.rna.tf32.f32 %0, %1;" : "=r"(u) : "f"(f));
    return u;
}

#define MMA_TF32(c, a, b0, b1)                                                  \
    asm volatile(                                                               \
        "mma.sync.aligned.m16n8k8.row.col.f32.tf32.tf32.f32 "                   \
        "{%0,%1,%2,%3}, {%4,%5,%6,%7}, {%8,%9}, {%0,%1,%2,%3};"                 \
        : "+f"(c[0]), "+f"(c[1]), "+f"(c[2]), "+f"(c[3])                        \
        : "r"(a[0]), "r"(a[1]), "r"(a[2]), "r"(a[3]), "r"(b0), "r"(b1))

__device__ __forceinline__ void cp_async8(uint32_t saddr, const float* gptr) {
    asm volatile("cp.async.ca.shared.global [%0], [%1], 8;" ::"r"(saddr),
                 "l"(gptr)
                 : "memory");
}

// ---------------------------------------------------------------------------
// Fused segment-GEMM + epilogue kernel.
// Block tile: 128 (batch rows) x 32 (state cols) x 4 segments.
// 256 threads = 8 warps as 4 (m) x 2 (n); warp tile 32 x 16 per segment.
// tf32 mma.sync m16n8k8, fp32 accumulate, full fp32 epilogue.
// ---------------------------------------------------------------------------
__global__ __launch_bounds__(256) void dendritic_kernel(
    const float* __restrict__ x,      // (8192, 2048)
    const float* __restrict__ W,      // (4, 2048, 2048)
    const float* __restrict__ b_seg,  // (4, 2048)
    const float* __restrict__ th,     // (4, 2048)
    float* __restrict__ out)          // (8192, 2048)
{
    __shared__ float sx[2][BM][SROW];
    __shared__ float sw[2][NSEG * BN][SROW];

    const int tid = threadIdx.x;
    const int bm = blockIdx.x;  // 0..63 (batch tiles)  -- fast dim for L2 reuse of W
    const int bn = blockIdx.y;  // 0..63 (state tiles)

    const int warpId = tid >> 5;
    const int lane = tid & 31;
    const int wm = warpId & 3;   // m offset = wm*32
    const int wn = warpId >> 2;  // n offset = wn*16
    const int g = lane >> 2;     // group (row within 8)
    const int qb = lane & 3;     // k quad

    // ---- cp.async per-thread assignments: 8-byte chunks ----
    // x tile: 128 rows x 16 cols -> 1024 chunks of 2 floats; 4 per thread.
    // W tile: 128 rows (4 segs * 32 d) x 16 cols -> same.
    const float* xg[4];
    const float* wg[4];
    uint32_t sx_addr[4], sw_addr[4];

    uint32_t sx_base = (uint32_t)__cvta_generic_to_shared(&sx[0][0][0]);
    uint32_t sw_base = (uint32_t)__cvta_generic_to_shared(&sw[0][0][0]);
    const uint32_t STAGE_BYTES = BM * SROW * 4;  // 10240 (same for sx and sw)

#pragma unroll
    for (int j = 0; j < 4; j++) {
        int chunk = tid + 256 * j;
        int r = chunk >> 3;
        int c = (chunk & 7) * 2;
        xg[j] = x + (size_t)(bm * BM + r) * DIN + c;
        sx_addr[j] = sx_base + (r * SROW + c) * 4;
        int s = r >> 5;
        int d = bn * BN + (r & 31);
        wg[j] = W + ((size_t)s * DSTATE + d) * DIN + c;
        sw_addr[j] = sw_base + (r * SROW + c) * 4;
    }

    // accumulators: [seg][mi][ni][4]
    float acc[NSEG][2][2][4];
#pragma unroll
    for (int s = 0; s < NSEG; s++)
#pragma unroll
        for (int mi = 0; mi < 2; mi++)
#pragma unroll
            for (int ni = 0; ni < 2; ni++)
#pragma unroll
                for (int e = 0; e < 4; e++) acc[s][mi][ni][e] = 0.f;

    // ---- prologue: load stage 0 ----
#pragma unroll
    for (int j = 0; j < 4; j++) cp_async8(sx_addr[j], xg[j]);
#pragma unroll
    for (int j = 0; j < 4; j++) cp_async8(sw_addr[j], wg[j]);
    asm volatile("cp.async.commit_group;" ::: "memory");

    for (int kt = 0; kt < NK; kt++) {
        const int st = kt & 1;
        asm volatile("cp.async.wait_group 0;" ::: "memory");
        __syncthreads();

        if (kt + 1 < NK) {
            const int nst = (kt + 1) & 1;
            const int koff = (kt + 1) * BK;
#pragma unroll
            for (int j = 0; j < 4; j++)
                cp_async8(sx_addr[j] + nst * STAGE_BYTES, xg[j] + koff);
#pragma unroll
            for (int j = 0; j < 4; j++)
                cp_async8(sw_addr[j] + nst * STAGE_BYTES, wg[j] + koff);
            asm volatile("cp.async.commit_group;" ::: "memory");
        }

#pragma unroll
        for (int k8 = 0; k8 < 2; k8++) {
            const int k0 = k8 * 8;
            uint32_t A[2][4];
#pragma unroll
            for (int mi = 0; mi < 2; mi++) {
                int r = wm * 32 + mi * 16 + g;
                A[mi][0] = f2tf(sx[st][r][k0 + qb]);
                A[mi][1] = f2tf(sx[st][r + 8][k0 + qb]);
                A[mi][2] = f2tf(sx[st][r][k0 + qb + 4]);
                A[mi][3] = f2tf(sx[st][r + 8][k0 + qb + 4]);
            }
#pragma unroll
            for (int s = 0; s < NSEG; s++) {
#pragma unroll
                for (int ni = 0; ni < 2; ni++) {
                    int dr = s * BN + wn * 16 + ni * 8 + g;
                    uint32_t B0 = f2tf(sw[st][dr][k0 + qb]);
                    uint32_t B1 = f2tf(sw[st][dr][k0 + qb + 4]);
#pragma unroll
                    for (int mi = 0; mi < 2; mi++) {
                        MMA_TF32(acc[s][mi][ni], A[mi], B0, B1);
                    }
                }
            }
        }
    }

    // ---- epilogue: bias, plateau, gate, sum + 0.1 * signed geo-mean ----
    const int bbase = bm * BM;
    const int dbase = bn * BN;

#pragma unroll
    for (int mi = 0; mi < 2; mi++) {
#pragma unroll
        for (int hh = 0; hh < 2; hh++) {
            const int rloc = wm * 32 + mi * 16 + g + hh * 8;
            const int brow = bbase + rloc;
            float gt[NSEG];
#pragma unroll
            for (int s = 0; s < NSEG; s++) gt[s] = g_gates[brow * 4 + s];
#pragma unroll
            for (int ni = 0; ni < 2; ni++) {
#pragma unroll
                for (int e = 0; e < 2; e++) {
                    const int d = dbase + wn * 16 + ni * 8 + qb * 2 + e;
                    float sumv = 0.f, prodv = 1.f;
#pragma unroll
                    for (int s = 0; s < NSEG; s++) {
                        float seg = acc[s][mi][ni][hh * 2 + e] + b_seg[s * DSTATE + d];
                        float z = 5.f * (seg - th[s * DSTATE + d]);
                        float p = 1.f / (1.f + __expf(-z));
                        float v = seg * p * gt[s];
                        sumv += v;
                        prodv *= v;
                    }
                    float r4 = sqrtf(sqrtf(fabsf(prodv)));
                    out[(size_t)brow * DSTATE + d] = sumv + 0.1f * copysignf(r4, prodv);
                }
            }
        }
    }
}

// ---------------------------------------------------------------------------
extern "C" void kernel_launch(void* const* d_in, const int* in_sizes, int n_in,
                              void* d_out, int out_size) {
    const float* x      = (const float*)d_in[0];
    const float* W_seg  = (const float*)d_in[1];
    const float* b_seg  = (const float*)d_in[2];
    const float* thresh = (const float*)d_in[3];
    const float* W_gate = (const float*)d_in[4];
    const float* b_gate = (const float*)d_in[5];
    float* out = (float*)d_out;

    (void)in_sizes; (void)n_in; (void)out_size;

    gate_kernel<<<BROWS / 8, 256>>>(x, W_gate, b_gate);

    dim3 grid(BROWS / BM, DSTATE / BN);  // (64, 64), m-fast
    dendritic_kernel<<<grid, 256>>>(x, W_seg, b_seg, thresh, out);
}

// round 5
// speedup vs baseline: 1.1500x; 1.1500x over previous
#include <cuda_runtime.h>
#include <cstdint>
#include <cstddef>

#define BROWS   8192
#define DIN     2048
#define DSTATE  2048
#define NSEG    4

#define BM 128
#define BN 32          // state-cols per block (x4 segments concurrently)
#define BK 16
#define NK (DIN / BK)  // 128
#define SROW 20        // smem row stride in floats (16 data + 4 pad)

// dynamic smem layout (floats): x[2][128][20] then w[2][128][20]
#define X_OFF(st)  ((st) * 2560)
#define W_OFF(st)  (5120 + (st) * 2560)
#define SMEM_FLOATS 10240   // 40 KB

__device__ float g_gates[BROWS * NSEG];

// ---------------------------------------------------------------------------
// Gate kernel: gates[b,s] = sigmoid(x[b,:] . W_gate[s,:] + b_gate[s])
// ---------------------------------------------------------------------------
__global__ __launch_bounds__(256) void gate_kernel(const float* __restrict__ x,
                                                   const float* __restrict__ Wg,
                                                   const float* __restrict__ bg) {
    int warp = threadIdx.x >> 5;
    int lane = threadIdx.x & 31;
    int b = blockIdx.x * 8 + warp;
    const float* xr = x + (size_t)b * DIN;

    float a0 = 0.f, a1 = 0.f, a2 = 0.f, a3 = 0.f;
    for (int i = lane * 4; i < DIN; i += 128) {
        float4 xv = *(const float4*)(xr + i);
        float4 w0 = *(const float4*)(Wg + 0 * DIN + i);
        float4 w1 = *(const float4*)(Wg + 1 * DIN + i);
        float4 w2 = *(const float4*)(Wg + 2 * DIN + i);
        float4 w3 = *(const float4*)(Wg + 3 * DIN + i);
        a0 += xv.x * w0.x + xv.y * w0.y + xv.z * w0.z + xv.w * w0.w;
        a1 += xv.x * w1.x + xv.y * w1.y + xv.z * w1.z + xv.w * w1.w;
        a2 += xv.x * w2.x + xv.y * w2.y + xv.z * w2.z + xv.w * w2.w;
        a3 += xv.x * w3.x + xv.y * w3.y + xv.z * w3.z + xv.w * w3.w;
    }
#pragma unroll
    for (int off = 16; off; off >>= 1) {
        a0 += __shfl_xor_sync(0xFFFFFFFFu, a0, off);
        a1 += __shfl_xor_sync(0xFFFFFFFFu, a1, off);
        a2 += __shfl_xor_sync(0xFFFFFFFFu, a2, off);
        a3 += __shfl_xor_sync(0xFFFFFFFFu, a3, off);
    }
    if (lane == 0) {
        g_gates[b * 4 + 0] = 1.f / (1.f + __expf(-(a0 + bg[0])));
        g_gates[b * 4 + 1] = 1.f / (1.f + __expf(-(a1 + bg[1])));
        g_gates[b * 4 + 2] = 1.f / (1.f + __expf(-(a2 + bg[2])));
        g_gates[b * 4 + 3] = 1.f / (1.f + __expf(-(a3 + bg[3])));
    }
}

// ---------------------------------------------------------------------------
// Helpers
// ---------------------------------------------------------------------------
__device__ __forceinline__ float rna_tf32(float f) {
    uint32_t u;
    asm("cvt.rna.tf32.f32 %0, %1;" : "=r"(u) : "f"(f));
    return __uint_as_float(u);
}

#define MMA_TF32(c, a, b0, b1)                                                  \
    asm volatile(                                                               \
        "mma.sync.aligned.m16n8k8.row.col.f32.tf32.tf32.f32 "                   \
        "{%0,%1,%2,%3}, {%4,%5,%6,%7}, {%8,%9}, {%0,%1,%2,%3};"                 \
        : "+f"(c[0]), "+f"(c[1]), "+f"(c[2]), "+f"(c[3])                        \
        : "r"(a[0]), "r"(a[1]), "r"(a[2]), "r"(a[3]), "r"(b0), "r"(b1))

// ---------------------------------------------------------------------------
// Fused segment-GEMM + epilogue kernel.
// Block tile: 128 (batch rows) x 32 (state cols) x 4 segments.
// 256 threads = 8 warps as 4 (m) x 2 (n); warp tile 32 x 16 per segment.
// tf32 values are rounded ONCE at the smem fill; mainloop is pure LDS + MMA.
// 2-stage smem ring, register prefetch distance 2, one sync per stage.
// ---------------------------------------------------------------------------
__global__ __launch_bounds__(256, 2) void dendritic_kernel(
    const float* __restrict__ x,      // (8192, 2048)
    const float* __restrict__ W,      // (4, 2048, 2048)
    const float* __restrict__ b_seg,  // (4, 2048)
    const float* __restrict__ th,     // (4, 2048)
    float* __restrict__ out)          // (8192, 2048)
{
    extern __shared__ float smf[];

    const int tid = threadIdx.x;
    const int bm = blockIdx.x;  // batch tile (fast dim -> W slice stays hot in L2)
    const int bn = blockIdx.y;  // state tile

    const int warpId = tid >> 5;
    const int lane = tid & 31;
    const int wm = warpId & 3;   // m offset = wm*32
    const int wn = warpId >> 2;  // n offset = wn*16
    const int g = lane >> 2;     // row within 8
    const int qb = lane & 3;     // k quad

    // ---- fill assignments: 1024 float4 chunks (512 x + 512 w), 4/thread ----
    const float* gp[4];
    int so[4];  // smem float offset within stage (stage stride 2560)
#pragma unroll
    for (int j = 0; j < 4; j++) {
        int chunk = tid + 256 * j;
        int row = chunk >> 2;        // 0..255
        int cc = (chunk & 3) * 4;    // float col 0,4,8,12
        if (row < 128) {
            gp[j] = x + (size_t)(bm * BM + row) * DIN + cc;
            so[j] = row * SROW + cc;             // into X region
        } else {
            int n = row - 128;
            int s = n >> 5;
            int d = bn * BN + (n & 31);
            gp[j] = W + ((size_t)s * DSTATE + d) * DIN + cc;
            so[j] = 5120 + n * SROW + cc;        // into W region
        }
    }

    float acc[NSEG][2][2][4];
#pragma unroll
    for (int s = 0; s < NSEG; s++)
#pragma unroll
        for (int mi = 0; mi < 2; mi++)
#pragma unroll
            for (int ni = 0; ni < 2; ni++)
#pragma unroll
                for (int e = 0; e < 4; e++) acc[s][mi][ni][e] = 0.f;

    // ---- prologue ----
    float4 v[4];
#pragma unroll
    for (int j = 0; j < 4; j++) v[j] = *(const float4*)gp[j];
#pragma unroll
    for (int j = 0; j < 4; j++) {
        float4 t;
        t.x = rna_tf32(v[j].x); t.y = rna_tf32(v[j].y);
        t.z = rna_tf32(v[j].z); t.w = rna_tf32(v[j].w);
        *(float4*)(smf + so[j]) = t;                       // stage 0
    }
    __syncthreads();
#pragma unroll
    for (int j = 0; j < 4; j++) v[j] = *(const float4*)(gp[j] + BK);  // kt=1 data

    for (int kt = 0; kt < NK; kt++) {
        const int st = kt & 1;

        // store prefetched (kt+1) into the other stage; prefetch kt+2
        if (kt + 1 < NK) {
            const int ot = st ^ 1;
#pragma unroll
            for (int j = 0; j < 4; j++) {
                float4 t;
                t.x = rna_tf32(v[j].x); t.y = rna_tf32(v[j].y);
                t.z = rna_tf32(v[j].z); t.w = rna_tf32(v[j].w);
                *(float4*)(smf + ot * 2560 + so[j]) = t;
            }
            if (kt + 2 < NK) {
#pragma unroll
                for (int j = 0; j < 4; j++)
                    v[j] = *(const float4*)(gp[j] + (size_t)(kt + 2) * BK);
            }
        }

        // compute from stage st (values pre-rounded: raw bit loads, no cvt)
        const float* sx = smf + st * 2560;
        const float* sw = smf + 5120 + st * 2560;
#pragma unroll
        for (int k8 = 0; k8 < 2; k8++) {
            const int k0 = k8 * 8;
            uint32_t A[2][4];
#pragma unroll
            for (int mi = 0; mi < 2; mi++) {
                int r = wm * 32 + mi * 16 + g;
                A[mi][0] = __float_as_uint(sx[r * SROW + k0 + qb]);
                A[mi][1] = __float_as_uint(sx[(r + 8) * SROW + k0 + qb]);
                A[mi][2] = __float_as_uint(sx[r * SROW + k0 + qb + 4]);
                A[mi][3] = __float_as_uint(sx[(r + 8) * SROW + k0 + qb + 4]);
            }
#pragma unroll
            for (int s = 0; s < NSEG; s++) {
#pragma unroll
                for (int ni = 0; ni < 2; ni++) {
                    int dr = s * BN + wn * 16 + ni * 8 + g;
                    uint32_t B0 = __float_as_uint(sw[dr * SROW + k0 + qb]);
                    uint32_t B1 = __float_as_uint(sw[dr * SROW + k0 + qb + 4]);
#pragma unroll
                    for (int mi = 0; mi < 2; mi++) {
                        MMA_TF32(acc[s][mi][ni], A[mi], B0, B1);
                    }
                }
            }
        }

        if (kt + 1 < NK) __syncthreads();
    }

    // ---- epilogue: bias, plateau, gate, sum + 0.1 * signed geo-mean ----
    const int bbase = bm * BM;
    const int dbase = bn * BN;

#pragma unroll
    for (int mi = 0; mi < 2; mi++) {
#pragma unroll
        for (int hh = 0; hh < 2; hh++) {
            const int rloc = wm * 32 + mi * 16 + g + hh * 8;
            const int brow = bbase + rloc;
            float4 gv = *(const float4*)(&g_gates[brow * 4]);
            float gt[NSEG] = {gv.x, gv.y, gv.z, gv.w};
#pragma unroll
            for (int ni = 0; ni < 2; ni++) {
#pragma unroll
                for (int e = 0; e < 2; e++) {
                    const int d = dbase + wn * 16 + ni * 8 + qb * 2 + e;
                    float sumv = 0.f, prodv = 1.f;
#pragma unroll
                    for (int s = 0; s < NSEG; s++) {
                        float seg = acc[s][mi][ni][hh * 2 + e] + b_seg[s * DSTATE + d];
                        float z = 5.f * (seg - th[s * DSTATE + d]);
                        float p = 1.f / (1.f + __expf(-z));
                        float vv = seg * p * gt[s];
                        sumv += vv;
                        prodv *= vv;
                    }
                    float r4 = sqrtf(sqrtf(fabsf(prodv)));
                    out[(size_t)brow * DSTATE + d] = sumv + 0.1f * copysignf(r4, prodv);
                }
            }
        }
    }
}

// ---------------------------------------------------------------------------
extern "C" void kernel_launch(void* const* d_in, const int* in_sizes, int n_in,
                              void* d_out, int out_size) {
    const float* x      = (const float*)d_in[0];
    const float* W_seg  = (const float*)d_in[1];
    const float* b_seg  = (const float*)d_in[2];
    const float* thresh = (const float*)d_in[3];
    const float* W_gate = (const float*)d_in[4];
    const float* b_gate = (const float*)d_in[5];
    float* out = (float*)d_out;
    (void)in_sizes; (void)n_in; (void)out_size;

    gate_kernel<<<BROWS / 8, 256>>>(x, W_gate, b_gate);

    dim3 grid(BROWS / BM, DSTATE / BN);  // (64, 64), bm fast
    dendritic_kernel<<<grid, 256, SMEM_FLOATS * sizeof(float)>>>(
        x, W_seg, b_seg, thresh, out);
}

// round 6
// speedup vs baseline: 1.2446x; 1.0823x over previous
#include <cuda_runtime.h>
#include <cstdint>
#include <cstddef>

#define BROWS   8192
#define DIN     2048
#define DSTATE  2048
#define NSEG    4

#define BM 128
#define BN 32          // state-cols per block (x4 segments concurrently)
#define BK 16
#define NK (DIN / BK)  // 128
#define SROW 20        // smem row stride in floats (16 data + 4 pad)
#define NSTAGE 4
#define STG_FLOATS (256 * SROW)              // 5120 floats = 20KB per stage
#define SMEM_FLOATS (NSTAGE * STG_FLOATS)    // 20480 floats = 80KB

__device__ float g_gates[BROWS * NSEG];
__device__ __align__(16) float g_xr[BROWS * DIN];           // 64 MB, tf32-rounded x
__device__ __align__(16) float g_wr[NSEG * DSTATE * DIN];   // 64 MB, tf32-rounded W

// ---------------------------------------------------------------------------
// Helpers
// ---------------------------------------------------------------------------
__device__ __forceinline__ float rna_tf32(float f) {
    uint32_t u;
    asm("cvt.rna.tf32.f32 %0, %1;" : "=r"(u) : "f"(f));
    return __uint_as_float(u);
}

#define MMA_TF32(c, a, b0, b1)                                                  \
    asm volatile(                                                               \
        "mma.sync.aligned.m16n8k8.row.col.f32.tf32.tf32.f32 "                   \
        "{%0,%1,%2,%3}, {%4,%5,%6,%7}, {%8,%9}, {%0,%1,%2,%3};"                 \
        : "+f"(c[0]), "+f"(c[1]), "+f"(c[2]), "+f"(c[3])                        \
        : "r"(a[0]), "r"(a[1]), "r"(a[2]), "r"(a[3]), "r"(b0), "r"(b1))

__device__ __forceinline__ void cp_async16(uint32_t saddr, const float* g) {
    asm volatile("cp.async.cg.shared.global [%0], [%1], 16;" ::"r"(saddr),
                 "l"(g) : "memory");
}
#define CP_COMMIT()  asm volatile("cp.async.commit_group;" ::: "memory")
#define CP_WAIT2()   asm volatile("cp.async.wait_group 2;" ::: "memory")

// ---------------------------------------------------------------------------
// Pre-round kernel: out[i] = round_to_tf32(in[i]) (rna). Vectorized.
// ---------------------------------------------------------------------------
__global__ __launch_bounds__(256) void preround_kernel(const float* __restrict__ in,
                                                       float* __restrict__ out,
                                                       int n4) {
    int i = blockIdx.x * blockDim.x + threadIdx.x;
    int stride = gridDim.x * blockDim.x;
    for (; i < n4; i += stride) {
        float4 v = ((const float4*)in)[i];
        v.x = rna_tf32(v.x); v.y = rna_tf32(v.y);
        v.z = rna_tf32(v.z); v.w = rna_tf32(v.w);
        ((float4*)out)[i] = v;
    }
}

// ---------------------------------------------------------------------------
// Gate kernel: gates[b,s] = sigmoid(x[b,:] . W_gate[s,:] + b_gate[s])
// ---------------------------------------------------------------------------
__global__ __launch_bounds__(256) void gate_kernel(const float* __restrict__ x,
                                                   const float* __restrict__ Wg,
                                                   const float* __restrict__ bg) {
    int warp = threadIdx.x >> 5;
    int lane = threadIdx.x & 31;
    int b = blockIdx.x * 8 + warp;
    const float* xr = x + (size_t)b * DIN;

    float a0 = 0.f, a1 = 0.f, a2 = 0.f, a3 = 0.f;
    for (int i = lane * 4; i < DIN; i += 128) {
        float4 xv = *(const float4*)(xr + i);
        float4 w0 = *(const float4*)(Wg + 0 * DIN + i);
        float4 w1 = *(const float4*)(Wg + 1 * DIN + i);
        float4 w2 = *(const float4*)(Wg + 2 * DIN + i);
        float4 w3 = *(const float4*)(Wg + 3 * DIN + i);
        a0 += xv.x * w0.x + xv.y * w0.y + xv.z * w0.z + xv.w * w0.w;
        a1 += xv.x * w1.x + xv.y * w1.y + xv.z * w1.z + xv.w * w1.w;
        a2 += xv.x * w2.x + xv.y * w2.y + xv.z * w2.z + xv.w * w2.w;
        a3 += xv.x * w3.x + xv.y * w3.y + xv.z * w3.z + xv.w * w3.w;
    }
#pragma unroll
    for (int off = 16; off; off >>= 1) {
        a0 += __shfl_xor_sync(0xFFFFFFFFu, a0, off);
        a1 += __shfl_xor_sync(0xFFFFFFFFu, a1, off);
        a2 += __shfl_xor_sync(0xFFFFFFFFu, a2, off);
        a3 += __shfl_xor_sync(0xFFFFFFFFu, a3, off);
    }
    if (lane == 0) {
        g_gates[b * 4 + 0] = 1.f / (1.f + __expf(-(a0 + bg[0])));
        g_gates[b * 4 + 1] = 1.f / (1.f + __expf(-(a1 + bg[1])));
        g_gates[b * 4 + 2] = 1.f / (1.f + __expf(-(a2 + bg[2])));
        g_gates[b * 4 + 3] = 1.f / (1.f + __expf(-(a3 + bg[3])));
    }
}

// ---------------------------------------------------------------------------
// Fused segment-GEMM + epilogue kernel.
// Block tile: 128 (batch rows) x 32 (state cols) x 4 segments.
// 256 threads = 8 warps as 4 (m) x 2 (n); warp tile 32 x 16 per segment.
// Inputs pre-rounded to tf32; producers are pure cp.async (4-stage ring),
// consumers pure LDS + MMA. One __syncthreads per k-tile.
// ---------------------------------------------------------------------------
__global__ __launch_bounds__(256, 2) void dendritic_kernel(
    const float* __restrict__ b_seg,  // (4, 2048)
    const float* __restrict__ th,     // (4, 2048)
    float* __restrict__ out)          // (8192, 2048)
{
    extern __shared__ float smf[];

    const int tid = threadIdx.x;
    const int bm = blockIdx.x;  // batch tile (fast dim -> W slice stays hot in L2)
    const int bn = blockIdx.y;  // state tile

    const int warpId = tid >> 5;
    const int lane = tid & 31;
    const int wm = warpId & 3;   // m offset = wm*32
    const int wn = warpId >> 2;  // n offset = wn*16
    const int g = lane >> 2;     // row within 8
    const int qb = lane & 3;     // k quad

    const uint32_t sm_base = (uint32_t)__cvta_generic_to_shared(smf);

    // ---- fill assignments: 1024 float4 chunks per stage (512 x + 512 w) ----
    const float* gp[4];
    uint32_t sa[4];  // smem byte addr within stage 0
#pragma unroll
    for (int j = 0; j < 4; j++) {
        int chunk = tid + 256 * j;
        int row = chunk >> 2;        // 0..255 (x rows 0..127, w rows 128..255)
        int cc = (chunk & 3) * 4;    // float col 0,4,8,12
        if (row < 128) {
            gp[j] = g_xr + (size_t)(bm * BM + row) * DIN + cc;
        } else {
            int n = row - 128;
            int s = n >> 5;
            int d = bn * BN + (n & 31);
            gp[j] = g_wr + ((size_t)s * DSTATE + d) * DIN + cc;
        }
        sa[j] = sm_base + (uint32_t)(row * SROW + cc) * 4;
    }

    float acc[NSEG][2][2][4];
#pragma unroll
    for (int s = 0; s < NSEG; s++)
#pragma unroll
        for (int mi = 0; mi < 2; mi++)
#pragma unroll
            for (int ni = 0; ni < 2; ni++)
#pragma unroll
                for (int e = 0; e < 4; e++) acc[s][mi][ni][e] = 0.f;

    // ---- prologue: issue stages 0..2 ----
#pragma unroll
    for (int p = 0; p < 3; p++) {
#pragma unroll
        for (int j = 0; j < 4; j++)
            cp_async16(sa[j] + p * (STG_FLOATS * 4), gp[j] + p * BK);
        CP_COMMIT();
    }

    for (int kt = 0; kt < NK; kt++) {
        const int st = kt & 3;
        CP_WAIT2();
        __syncthreads();  // stage kt visible to all; stage (kt-1) compute done

        if (kt + 3 < NK) {
            const int ns = (kt + 3) & 3;
#pragma unroll
            for (int j = 0; j < 4; j++)
                cp_async16(sa[j] + ns * (STG_FLOATS * 4), gp[j] + (kt + 3) * BK);
            CP_COMMIT();
        }

        const float* sx = smf + st * STG_FLOATS;
        const float* sw = smf + st * STG_FLOATS + 2560;
#pragma unroll
        for (int k8 = 0; k8 < 2; k8++) {
            const int k0 = k8 * 8;
            uint32_t A[2][4];
#pragma unroll
            for (int mi = 0; mi < 2; mi++) {
                int r = wm * 32 + mi * 16 + g;
                A[mi][0] = __float_as_uint(sx[r * SROW + k0 + qb]);
                A[mi][1] = __float_as_uint(sx[(r + 8) * SROW + k0 + qb]);
                A[mi][2] = __float_as_uint(sx[r * SROW + k0 + qb + 4]);
                A[mi][3] = __float_as_uint(sx[(r + 8) * SROW + k0 + qb + 4]);
            }
#pragma unroll
            for (int s = 0; s < NSEG; s++) {
#pragma unroll
                for (int ni = 0; ni < 2; ni++) {
                    int dr = s * BN + wn * 16 + ni * 8 + g;
                    uint32_t B0 = __float_as_uint(sw[dr * SROW + k0 + qb]);
                    uint32_t B1 = __float_as_uint(sw[dr * SROW + k0 + qb + 4]);
#pragma unroll
                    for (int mi = 0; mi < 2; mi++) {
                        MMA_TF32(acc[s][mi][ni], A[mi], B0, B1);
                    }
                }
            }
        }
    }

    // ---- epilogue: bias, plateau, gate, sum + 0.1 * signed geo-mean ----
    const int bbase = bm * BM;
    const int dbase = bn * BN;

#pragma unroll
    for (int mi = 0; mi < 2; mi++) {
#pragma unroll
        for (int hh = 0; hh < 2; hh++) {
            const int rloc = wm * 32 + mi * 16 + g + hh * 8;
            const int brow = bbase + rloc;
            float4 gv = *(const float4*)(&g_gates[brow * 4]);
            float gt[NSEG] = {gv.x, gv.y, gv.z, gv.w};
#pragma unroll
            for (int ni = 0; ni < 2; ni++) {
#pragma unroll
                for (int e = 0; e < 2; e++) {
                    const int d = dbase + wn * 16 + ni * 8 + qb * 2 + e;
                    float sumv = 0.f, prodv = 1.f;
#pragma unroll
                    for (int s = 0; s < NSEG; s++) {
                        float seg = acc[s][mi][ni][hh * 2 + e] + b_seg[s * DSTATE + d];
                        float z = 5.f * (seg - th[s * DSTATE + d]);
                        float p = 1.f / (1.f + __expf(-z));
                        float vv = seg * p * gt[s];
                        sumv += vv;
                        prodv *= vv;
                    }
                    float r4 = sqrtf(sqrtf(fabsf(prodv)));
                    out[(size_t)brow * DSTATE + d] = sumv + 0.1f * copysignf(r4, prodv);
                }
            }
        }
    }
}

// ---------------------------------------------------------------------------
extern "C" void kernel_launch(void* const* d_in, const int* in_sizes, int n_in,
                              void* d_out, int out_size) {
    const float* x      = (const float*)d_in[0];
    const float* W_seg  = (const float*)d_in[1];
    const float* b_seg  = (const float*)d_in[2];
    const float* thresh = (const float*)d_in[3];
    const float* W_gate = (const float*)d_in[4];
    const float* b_gate = (const float*)d_in[5];
    float* out = (float*)d_out;
    (void)in_sizes; (void)n_in; (void)out_size;

    float* gx;
    float* gw;
    cudaGetSymbolAddress((void**)&gx, g_xr);
    cudaGetSymbolAddress((void**)&gw, g_wr);

    cudaFuncSetAttribute(dendritic_kernel,
                         cudaFuncAttributeMaxDynamicSharedMemorySize,
                         SMEM_FLOATS * sizeof(float));

    preround_kernel<<<1184, 256>>>(x, gx, BROWS * DIN / 4);
    preround_kernel<<<1184, 256>>>(W_seg, gw, NSEG * DSTATE * DIN / 4);
    gate_kernel<<<BROWS / 8, 256>>>(x, W_gate, b_gate);

    dim3 grid(BROWS / BM, DSTATE / BN);  // (64, 64), bm fast
    dendritic_kernel<<<grid, 256, SMEM_FLOATS * sizeof(float)>>>(
        b_seg, thresh, out);
}